// round 5
// baseline (speedup 1.0000x reference)
#include <cuda_runtime.h>
#include <math.h>

#define BA 2048          // B*A
#define E  256
#define H  128
#define KF 12
#define NORM 0.08838834764831845f   // 1/sqrt(128)

// Scratch (static __device__ to satisfy no-alloc rule)
__device__ float g_qk [BA * H];              // vs0 @ (Wq @ Wk^T)
__device__ float g_wve[BA * H];              // softmax-weighted sum of ve rows
__device__ float g_veC[(size_t)BA * KF * H]; // gathered top-12 entity rows
__device__ float g_M  [H * H];               // Wq @ Wk^T
__device__ float g_P  [H * H];               // Wv @ W1[H:,:]

// ---------------------------------------------------------------------------
// fp32x2 packed helpers (Blackwell)
// ---------------------------------------------------------------------------
__device__ __forceinline__ unsigned long long pack_dup(float w) {
    unsigned long long r;
    asm("mov.b64 %0, {%1, %1};" : "=l"(r) : "f"(w));
    return r;
}
__device__ __forceinline__ void fma2(unsigned long long& acc,
                                     unsigned long long a, unsigned long long b) {
    asm("fma.rn.f32x2 %0, %1, %2, %0;" : "+l"(acc) : "l"(a), "l"(b));
}
__device__ __forceinline__ void unpack2(unsigned long long v, float& lo, float& hi) {
    asm("mov.b64 {%0, %1}, %2;" : "=f"(lo), "=f"(hi) : "l"(v));
}

// ---------------------------------------------------------------------------
// Kernel 1: tiny 128x128 weight products. grid (128, 2), 128 threads.
// ---------------------------------------------------------------------------
__global__ void prep_MP(const float* __restrict__ Wq, const float* __restrict__ Wk,
                        const float* __restrict__ Wv, const float* __restrict__ W1)
{
    __shared__ float arow[H];
    int r = blockIdx.x;
    int c = threadIdx.x;
    int m = blockIdx.y;
    const float* A = (m == 0) ? Wq : Wv;
    arow[c] = A[r * H + c];
    __syncthreads();

    float acc = 0.0f;
    if (m == 0) {
        const float4* wk4 = (const float4*)(Wk + c * H);
        #pragma unroll 8
        for (int d4 = 0; d4 < H / 4; d4++) {
            float4 w = wk4[d4];
            acc += arow[4 * d4 + 0] * w.x + arow[4 * d4 + 1] * w.y
                 + arow[4 * d4 + 2] * w.z + arow[4 * d4 + 3] * w.w;
        }
        g_M[r * H + c] = acc;
    } else {
        #pragma unroll 8
        for (int d = 0; d < H; d++)
            acc = fmaf(arow[d], W1[(H + d) * H + c], acc);
        g_P[r * H + c] = acc;
    }
}

// ---------------------------------------------------------------------------
// Kernel 2: qk = vs0 @ M   ([2048,128] @ [128,128]). grid 128, 128 threads.
// ---------------------------------------------------------------------------
__global__ void qk_kernel(const float* __restrict__ vs)
{
    __shared__ float Ms[H * H];
    __shared__ float xs[16 * H];
    int c  = threadIdx.x;
    int i0 = blockIdx.x * 16;
    for (int k = 0; k < H; k++) Ms[k * H + c] = g_M[k * H + c];
    for (int r = 0; r < 16; r++) xs[r * H + c] = vs[(i0 + r) * H + c];
    __syncthreads();
    for (int r = 0; r < 16; r++) {
        float acc = 0.0f;
        #pragma unroll 8
        for (int h = 0; h < H; h++)
            acc = fmaf(xs[r * H + h], Ms[h * H + c], acc);
        g_qk[(i0 + r) * H + c] = acc;
    }
}

// ---------------------------------------------------------------------------
// Kernel 3: MAIN. One CTA per (b,a), 256 threads, single pass over ve.
// Online softmax + cheap multireduce: 6 shuffles per 4-entity dot, 2 MUFU.
// ---------------------------------------------------------------------------
__global__ void __launch_bounds__(256)
main_kernel(const float* __restrict__ ve, const int* __restrict__ dead)
{
    __shared__ float scomp[E];        // compat (with -inf dead mask)
    __shared__ float swm[8], sws[8];  // per-warp online max / sum
    __shared__ float sacc[8 * H];     // per-warp weighted accumulators
    __shared__ int   ssel[KF];

    const int i   = blockIdx.x;
    const int tid = threadIdx.x;
    const int w   = tid >> 5;
    const int l   = tid & 31;
    const unsigned FULL = 0xffffffffu;

    const float4* ve4 = (const float4*)(ve + (size_t)i * E * H);
    const float4  qk4 = ((const float4*)(g_qk + (size_t)i * H))[l];
    const int*    dr  = dead + i * E;

    float  m = -INFINITY, s = 0.0f;
    float4 acc = make_float4(0.f, 0.f, 0.f, 0.f);

    #pragma unroll 2
    for (int eo = 0; eo < 32; eo += 4) {
        const int e = w * 32 + eo;
        float4 r0 = ve4[(e + 0) * 32 + l];
        float4 r1 = ve4[(e + 1) * 32 + l];
        float4 r2 = ve4[(e + 2) * 32 + l];
        float4 r3 = ve4[(e + 3) * 32 + l];
        float s0 = r0.x * qk4.x + r0.y * qk4.y + r0.z * qk4.z + r0.w * qk4.w;
        float s1 = r1.x * qk4.x + r1.y * qk4.y + r1.z * qk4.z + r1.w * qk4.w;
        float s2 = r2.x * qk4.x + r2.y * qk4.y + r2.z * qk4.z + r2.w * qk4.w;
        float s3 = r3.x * qk4.x + r3.y * qk4.y + r3.z * qk4.z + r3.w * qk4.w;

        // multireduce: after this, a[l] = full dot of entity e+(l&3),
        // replicated across lanes with equal (l&3).
        float a01 = (l & 1) ? s1 : s0;
        float b01 = (l & 1) ? s0 : s1;
        a01 += __shfl_xor_sync(FULL, b01, 1);
        float a23 = (l & 1) ? s3 : s2;
        float b23 = (l & 1) ? s2 : s3;
        a23 += __shfl_xor_sync(FULL, b23, 1);
        float a  = (l & 2) ? a23 : a01;
        float bx = (l & 2) ? a01 : a23;
        a += __shfl_xor_sync(FULL, bx, 2);
        a += __shfl_xor_sync(FULL, a, 4);
        a += __shfl_xor_sync(FULL, a, 8);
        a += __shfl_xor_sync(FULL, a, 16);

        const int dmask = dr[e + (l & 3)];
        float cmp = dmask ? -INFINITY : NORM * a;
        if (l < 4) scomp[e + l] = cmp;

        // max over the 4 entities (replicated), then online update
        float cm = fmaxf(cmp, __shfl_xor_sync(FULL, cmp, 1));
        cm = fmaxf(cm, __shfl_xor_sync(FULL, cm, 2));
        float mn = fmaxf(m, cm);
        if (mn != -INFINITY) {
            float sc = __expf(m - mn);      // m = -inf -> 0
            float p  = __expf(cmp - mn);    // cmp = -inf -> 0
            float p0 = __shfl_sync(FULL, p, 0, 4);
            float p1 = __shfl_sync(FULL, p, 1, 4);
            float p2 = __shfl_sync(FULL, p, 2, 4);
            float p3 = __shfl_sync(FULL, p, 3, 4);
            s = fmaf(s, sc, p0 + p1 + p2 + p3);
            acc.x = fmaf(acc.x, sc, p0 * r0.x + p1 * r1.x + p2 * r2.x + p3 * r3.x);
            acc.y = fmaf(acc.y, sc, p0 * r0.y + p1 * r1.y + p2 * r2.y + p3 * r3.y);
            acc.z = fmaf(acc.z, sc, p0 * r0.z + p1 * r1.z + p2 * r2.z + p3 * r3.z);
            acc.w = fmaf(acc.w, sc, p0 * r0.w + p1 * r1.w + p2 * r2.w + p3 * r3.w);
            m = mn;
        }
    }

    if (l == 0) { swm[w] = m; sws[w] = s; }
    ((float4*)sacc)[w * 32 + l] = acc;
    __syncthreads();

    // ---- cross-warp combine -> wve (threads 0..127) ----
    if (tid < H) {
        float M = swm[0];
        #pragma unroll
        for (int j = 1; j < 8; j++) M = fmaxf(M, swm[j]);
        float tot = 0.0f, sum = 0.0f;
        if (M != -INFINITY) {
            #pragma unroll
            for (int j = 0; j < 8; j++) {
                float f = __expf(swm[j] - M);
                tot = fmaf(sws[j], f, tot);
                sum = fmaf(f, sacc[j * H + tid], sum);
            }
        }
        g_wve[(size_t)i * H + tid] = (tot > 0.0f) ? sum / tot : 0.0f;
    }

    // ---- top-12 on compat (warp 0): desc value, asc index ties ----
    if (w == 0) {
        unsigned sel = 0;   // bit j: my entity j*32+l already selected
        for (int k = 0; k < KF; k++) {
            float bv = -INFINITY; int bi = 0x7fffffff;
            #pragma unroll
            for (int j = 0; j < 8; j++) {
                if ((sel >> j) & 1u) continue;
                int e = j * 32 + l;
                float v = scomp[e];
                if (v > bv || (v == bv && e < bi)) { bv = v; bi = e; }
            }
            #pragma unroll
            for (int off = 16; off; off >>= 1) {
                float ov = __shfl_xor_sync(FULL, bv, off);
                int   oi = __shfl_xor_sync(FULL, bi, off);
                if (ov > bv || (ov == bv && oi < bi)) { bv = ov; bi = oi; }
            }
            if ((bi & 31) == l) sel |= 1u << (bi >> 5);
            if (l == 0) ssel[k] = bi;
        }
    }
    __syncthreads();

    // ---- gather selected rows (8 warps, strided over 12) ----
    for (int k = w; k < KF; k += 8) {
        int e = ssel[k];
        ((float4*)g_veC)[((size_t)i * KF + k) * 32 + l] = ve4[e * 32 + l];
    }
}

// ---------------------------------------------------------------------------
// Kernel 4: v_M = relu([vs0|wve] @ [W1a;P] + b1). K=256, 8 chunks of 32.
// 256 blocks x 128 threads, 8 rows/block. f32x2 inner, transposed x tile.
// ---------------------------------------------------------------------------
#define RBM 8
__global__ void __launch_bounds__(128)
vM_kernel(const float* __restrict__ vs, const float* __restrict__ W1,
          const float* __restrict__ b1, float* __restrict__ out)
{
    __shared__ float sw[32 * H];        // 16 KB weight chunk, row-major
    __shared__ float sxT[32 * RBM];     // transposed x: sxT[jj][r]
    const int c  = threadIdx.x;
    const int i0 = blockIdx.x * RBM;

    unsigned long long acc2[RBM / 2];
    #pragma unroll
    for (int p = 0; p < RBM / 2; p++) acc2[p] = pack_dup(0.0f);

    #pragma unroll 1
    for (int ch = 0; ch < 8; ch++) {
        const int j0 = ch * 32;
        const float* wsrc = (j0 < 128) ? (W1 + (size_t)j0 * H)
                                       : (g_P + (size_t)(j0 - 128) * H);
        const float4* w4  = (const float4*)wsrc;
        float4*       sw4 = (float4*)sw;
        #pragma unroll
        for (int t = 0; t < 8; t++) sw4[t * 128 + c] = w4[t * 128 + c];
        if (c < 64) {
            int r = c & 7, jj4 = c >> 3;
            const float* src = (j0 < 128)
                ? (vs    + (size_t)(i0 + r) * H + j0 + jj4 * 4)
                : (g_wve + (size_t)(i0 + r) * H + (j0 - 128) + jj4 * 4);
            float4 v = *(const float4*)src;
            sxT[(jj4 * 4 + 0) * RBM + r] = v.x;
            sxT[(jj4 * 4 + 1) * RBM + r] = v.y;
            sxT[(jj4 * 4 + 2) * RBM + r] = v.z;
            sxT[(jj4 * 4 + 3) * RBM + r] = v.w;
        }
        __syncthreads();
        #pragma unroll
        for (int sub = 0; sub < 4; sub++) {
            unsigned long long wp[8];
            #pragma unroll
            for (int k = 0; k < 8; k++)
                wp[k] = pack_dup(sw[(sub * 8 + k) * H + c]);
            #pragma unroll
            for (int k = 0; k < 8; k++) {
                int jj = sub * 8 + k;
                ulonglong2 xa = *(const ulonglong2*)&sxT[jj * RBM];
                fma2(acc2[0], xa.x, wp[k]);
                fma2(acc2[1], xa.y, wp[k]);
                ulonglong2 xb = *(const ulonglong2*)&sxT[jj * RBM + 4];
                fma2(acc2[2], xb.x, wp[k]);
                fma2(acc2[3], xb.y, wp[k]);
            }
        }
        __syncthreads();
    }
    float bb = b1[c];
    #pragma unroll
    for (int p = 0; p < RBM / 2; p++) {
        float lo, hi;
        unpack2(acc2[p], lo, hi);
        out[(size_t)BA * H + (size_t)(i0 + 2 * p + 0) * H + c] = fmaxf(lo + bb, 0.0f);
        out[(size_t)BA * H + (size_t)(i0 + 2 * p + 1) * H + c] = fmaxf(hi + bb, 0.0f);
    }
}

// ---------------------------------------------------------------------------
// Kernel 5: v_C = relu([vs0 | veC] @ W2 + b2). [2048,1664]@[1664,128].
// 128 blocks x 256 threads, 16 rows/block, K split in two halves (26 chunks).
// f32x2 inner, transposed x tile, weights in registers per 8-K sub-block.
// ---------------------------------------------------------------------------
#define RBC 16
__global__ void __launch_bounds__(256)
vC_kernel(const float* __restrict__ vs, const float* __restrict__ W2,
          const float* __restrict__ b2, float* __restrict__ out)
{
    __shared__ float sw [2][32 * H];      // 32 KB
    __shared__ float sxT[2][32 * RBC];    // 4 KB: sxT[jj][r]
    __shared__ float sred[RBC * H];       // 8 KB
    const int tid = threadIdx.x;
    const int hf  = tid >> 7;             // K-half
    const int c   = tid & 127;            // output column
    const int i0  = blockIdx.x * RBC;

    unsigned long long acc2[RBC / 2];
    #pragma unroll
    for (int p = 0; p < RBC / 2; p++) acc2[p] = pack_dup(0.0f);

    #pragma unroll 1
    for (int ch = 0; ch < 26; ch++) {
        const int j0 = (hf * 26 + ch) * 32;
        const float4* w4  = (const float4*)(W2 + (size_t)j0 * H);
        float4*       sw4 = (float4*)sw[hf];
        #pragma unroll
        for (int t = 0; t < 8; t++) sw4[t * 128 + c] = w4[t * 128 + c];
        // x tile transpose: 64 threads/half, each 1 float4 read + 4 scattered
        // passes over (r, jj4) grid: 16 rows x 8 jj4 = 128 cells, 2 per thread
        #pragma unroll
        for (int pass = 0; pass < 2; pass++) {
            if (c < 64) {
                int cell = pass * 64 + c;
                int r = cell & 15, jj4 = cell >> 4;
                const float* src = (j0 < 128)
                    ? (vs    + (size_t)(i0 + r) * H + j0 + jj4 * 4)
                    : (g_veC + (size_t)(i0 + r) * (KF * H) + (j0 - 128) + jj4 * 4);
                float4 v = *(const float4*)src;
                sxT[hf][(jj4 * 4 + 0) * RBC + r] = v.x;
                sxT[hf][(jj4 * 4 + 1) * RBC + r] = v.y;
                sxT[hf][(jj4 * 4 + 2) * RBC + r] = v.z;
                sxT[hf][(jj4 * 4 + 3) * RBC + r] = v.w;
            }
        }
        __syncthreads();
        #pragma unroll
        for (int sub = 0; sub < 4; sub++) {
            unsigned long long wp[8];
            #pragma unroll
            for (int k = 0; k < 8; k++)
                wp[k] = pack_dup(sw[hf][(sub * 8 + k) * H + c]);
            #pragma unroll
            for (int k = 0; k < 8; k++) {
                int jj = sub * 8 + k;
                const ulonglong2* xr = (const ulonglong2*)&sxT[hf][jj * RBC];
                ulonglong2 xa = xr[0];
                fma2(acc2[0], xa.x, wp[k]);
                fma2(acc2[1], xa.y, wp[k]);
                ulonglong2 xb = xr[1];
                fma2(acc2[2], xb.x, wp[k]);
                fma2(acc2[3], xb.y, wp[k]);
                ulonglong2 xc = xr[2];
                fma2(acc2[4], xc.x, wp[k]);
                fma2(acc2[5], xc.y, wp[k]);
                ulonglong2 xd = xr[3];
                fma2(acc2[6], xd.x, wp[k]);
                fma2(acc2[7], xd.y, wp[k]);
            }
        }
        __syncthreads();
    }

    if (hf) {
        #pragma unroll
        for (int p = 0; p < RBC / 2; p++) {
            float lo, hi;
            unpack2(acc2[p], lo, hi);
            sred[(2 * p + 0) * H + c] = lo;
            sred[(2 * p + 1) * H + c] = hi;
        }
    }
    __syncthreads();
    if (!hf) {
        float bb = b2[c];
        #pragma unroll
        for (int p = 0; p < RBC / 2; p++) {
            float lo, hi;
            unpack2(acc2[p], lo, hi);
            out[(size_t)(i0 + 2 * p + 0) * H + c] =
                fmaxf(lo + sred[(2 * p + 0) * H + c] + bb, 0.0f);
            out[(size_t)(i0 + 2 * p + 1) * H + c] =
                fmaxf(hi + sred[(2 * p + 1) * H + c] + bb, 0.0f);
        }
    }
}

// ---------------------------------------------------------------------------
extern "C" void kernel_launch(void* const* d_in, const int* in_sizes, int n_in,
                              void* d_out, int out_size)
{
    const float* vs   = (const float*)d_in[0];
    const float* ve   = (const float*)d_in[1];
    const int*   dead = (const int*)  d_in[2];
    const float* Wq   = (const float*)d_in[3];
    const float* Wk   = (const float*)d_in[4];
    const float* Wv   = (const float*)d_in[5];
    const float* W1   = (const float*)d_in[6];
    const float* b1   = (const float*)d_in[7];
    const float* W2   = (const float*)d_in[8];
    const float* b2   = (const float*)d_in[9];
    float* out = (float*)d_out;

    prep_MP   <<<dim3(128, 2), 128>>>(Wq, Wk, Wv, W1);
    qk_kernel <<<128, 128>>>(vs);
    main_kernel<<<BA, 256>>>(ve, dead);
    vM_kernel <<<BA / RBM, 128>>>(vs, W1, b1, out);
    vC_kernel <<<BA / RBC, 256>>>(vs, W2, b2, out);
}